// round 3
// baseline (speedup 1.0000x reference)
#include <cuda_runtime.h>
#include <math.h>

#define VDIM 1024
#define MAXB 8
#define MAXT 256
#define MAXU 65

// Scratch (allocation-free rule: __device__ globals)
__device__ float g_lp_blank[MAXB * MAXT * MAXU];          // [b][t][u]
__device__ float g_lp_label[MAXB * MAXT * (MAXU - 1)];    // [b][t][u<U-1]
__device__ float g_loss[MAXB];

// ---------------------------------------------------------------------------
// Kernel 1: per-row (b,t,u) log-softmax over V=1024, emit blank & label lp.
// One warp per row: 8 x float4 per lane (32 floats) kept in registers,
// warp-shuffle max + sum(exp) reductions. No shared memory, no block sync.
// ---------------------------------------------------------------------------
__global__ void __launch_bounds__(256) softmax_pick_kernel(
    const float* __restrict__ acts, const int* __restrict__ labels,
    int B, int T, int U, int nRows)
{
    int gw   = (blockIdx.x * blockDim.x + threadIdx.x) >> 5;  // global warp id = row
    int lane = threadIdx.x & 31;
    if (gw >= nRows) return;

    const float4* row = reinterpret_cast<const float4*>(acts) + (size_t)gw * (VDIM / 4);

    float4 v[8];
#pragma unroll
    for (int k = 0; k < 8; ++k)
        v[k] = row[lane + 32 * k];            // coalesced: lane-contiguous float4s

    // max over 1024
    float m = -INFINITY;
#pragma unroll
    for (int k = 0; k < 8; ++k)
        m = fmaxf(m, fmaxf(fmaxf(v[k].x, v[k].y), fmaxf(v[k].z, v[k].w)));
#pragma unroll
    for (int o = 16; o > 0; o >>= 1)
        m = fmaxf(m, __shfl_xor_sync(0xffffffffu, m, o));

    // sum exp(x - m)
    float s = 0.f;
#pragma unroll
    for (int k = 0; k < 8; ++k) {
        s += __expf(v[k].x - m);
        s += __expf(v[k].y - m);
        s += __expf(v[k].z - m);
        s += __expf(v[k].w - m);
    }
#pragma unroll
    for (int o = 16; o > 0; o >>= 1)
        s += __shfl_xor_sync(0xffffffffu, s, o);

    float logZ = m + __logf(s);

    // row -> (b,t,u)
    int u  = gw % U;
    int bt = gw / U;
    int t  = bt % T;
    int b  = bt / T;

    // blank = element 0 (lane 0, k 0, comp x)
    if (lane == 0)
        g_lp_blank[gw] = v[0].x - logZ;

    // label gather (u < U-1 only)
    if (u < U - 1) {
        int lbl = labels[b * (U - 1) + u];    // in [1, V)
        int q   = lbl >> 2;                   // which float4 globally
        if (lane == (q & 31)) {
            int kq = q >> 5;
            int c  = lbl & 3;
#pragma unroll
            for (int k = 0; k < 8; ++k)
                if (k == kq) {                // static unroll keeps v[] in regs
                    float4 w = v[k];
                    float  x = (c == 0) ? w.x : (c == 1) ? w.y : (c == 2) ? w.z : w.w;
                    g_lp_label[(b * T + t) * (U - 1) + u] = x - logZ;
                }
        }
    }
}

// ---------------------------------------------------------------------------
// Kernel 2: alpha wavefront DP, one block per batch.
//   alpha[0][u]   = alpha[0][u-1] + label[0][u-1]        (cumsum)
//   alpha[t][0]   = alpha[t-1][0] + blank[t-1][0]
//   alpha[t][u]   = logaddexp(alpha[t-1][u] + blank[t-1][u],
//                             alpha[t][u-1] + label[t][u-1])
// Anti-diagonal d = t+u; cells on a diagonal depend only on diagonal d-1.
// ---------------------------------------------------------------------------
__device__ __forceinline__ float logaddexpf_(float x, float y)
{
    float m = fmaxf(x, y);
    return m + __logf(1.f + __expf(fminf(x, y) - m));
}

extern __shared__ __align__(16) float smem2[];

__global__ void __launch_bounds__(256) alpha_kernel(
    const int* __restrict__ act_lens, const int* __restrict__ label_lens,
    int T, int U)
{
    int b   = blockIdx.x;
    int tid = threadIdx.x;
    int U1  = U - 1;

    float* sb = smem2;           // blank slice  [T][U]
    float* sl = smem2 + T * U;   // label slice  [T][U-1]
    __shared__ float diag[2][MAXU + 1];

    // preload batch slices into shared (float4, sizes are multiples of 4)
    {
        const float4* gb = reinterpret_cast<const float4*>(g_lp_blank + (size_t)b * T * U);
        float4* sb4 = reinterpret_cast<float4*>(sb);
        int nb4 = (T * U) >> 2;
        for (int i = tid; i < nb4; i += blockDim.x) sb4[i] = gb[i];

        const float4* gl = reinterpret_cast<const float4*>(g_lp_label + (size_t)b * T * U1);
        float4* sl4 = reinterpret_cast<float4*>(sl);
        int nl4 = (T * U1) >> 2;
        for (int i = tid; i < nl4; i += blockDim.x) sl4[i] = gl[i];
    }

    int tcap = act_lens[b] - 1;
    int ucap = label_lens[b];

    if (tid == 0) {
        diag[0][0] = 0.f;                               // alpha[0][0]
        if (tcap == 0 && ucap == 0)
            g_loss[b] = -(0.f + sb[0]);                 // degenerate capture
    }
    __syncthreads();

    int u = tid;
    int D = T + U - 1;
    for (int d = 1; d < D; ++d) {
        float* prev = diag[(d - 1) & 1];
        float* cur  = diag[d & 1];
        if (u < U) {
            int t = d - u;
            if (t >= 0 && t < T) {
                float a;
                if (t == 0) {
                    a = prev[u - 1] + sl[u - 1];                       // cumsum row
                } else if (u == 0) {
                    a = prev[0] + sb[(t - 1) * U];                     // blank column
                } else {
                    float x = prev[u]     + sb[(t - 1) * U + u];
                    float y = prev[u - 1] + sl[t * U1 + (u - 1)];
                    a = logaddexpf_(x, y);
                }
                cur[u] = a;
                if (t == tcap && u == ucap)
                    g_loss[b] = -(a + sb[tcap * U + ucap]);
            }
        }
        __syncthreads();
    }
}

// ---------------------------------------------------------------------------
// Kernel 3: mean of per-batch costs -> d_out[0]
// ---------------------------------------------------------------------------
__global__ void finalize_kernel(float* __restrict__ out, int B)
{
    int lane = threadIdx.x;
    float v = (lane < B) ? g_loss[lane] : 0.f;
#pragma unroll
    for (int o = 16; o > 0; o >>= 1)
        v += __shfl_xor_sync(0xffffffffu, v, o);
    if (lane == 0)
        out[0] = v / (float)B;
}

// ---------------------------------------------------------------------------
extern "C" void kernel_launch(void* const* d_in, const int* in_sizes, int n_in,
                              void* d_out, int out_size)
{
    const float* acts       = (const float*)d_in[0];
    const int*   labels     = (const int*)d_in[1];
    const int*   act_lens   = (const int*)d_in[2];
    const int*   label_lens = (const int*)d_in[3];

    int B  = in_sizes[2];                 // 8
    int U1 = in_sizes[1] / B;             // 64
    int U  = U1 + 1;                      // 65
    long long total = in_sizes[0];
    int T  = (int)(total / ((long long)B * U * VDIM));   // 256

    int nRows = B * T * U;                                // 133,120
    int blocks = (nRows + 7) / 8;                         // 8 warps / block
    softmax_pick_kernel<<<blocks, 256>>>(acts, labels, B, T, U, nRows);

    int smemBytes = (T * U + T * U1) * (int)sizeof(float);  // ~132 KB
    cudaFuncSetAttribute(alpha_kernel,
                         cudaFuncAttributeMaxDynamicSharedMemorySize, smemBytes);
    alpha_kernel<<<B, 256, smemBytes>>>(act_lens, label_lens, T, U);

    finalize_kernel<<<1, 32>>>((float*)d_out, B);
}